// round 3
// baseline (speedup 1.0000x reference)
#include <cuda_runtime.h>
#include <cuda_bf16.h>
#include <cstdint>
#include <cstddef>

#define B_ 4
#define NT 16384
#define DM 128
#define SPG 32
#define CH (NT / SPG)      // 512 tokens per G-split CTA
#define ITG (CH / 16)      // 32 k-steps

// Scratch (__device__ globals). g_part: G partials [32][4][128][128], reused as
// Wfin h-partials [8*4][128][128].
static __device__ float g_part[SPG * B_ * DM * DM];
static __device__ float g_G   [B_ * DM * DM];
static __device__ float g_T1  [32 * 64 * DM];
static __device__ float g_T3  [32 * DM * 64];
static __device__ float g_Wfin[B_ * DM * DM];

// ---------------- helpers ----------------
__device__ __forceinline__ unsigned long long pack2(float x, float y) {
    unsigned long long r; asm("mov.b64 %0, {%1,%2};" : "=l"(r) : "f"(x), "f"(y)); return r;
}
__device__ __forceinline__ void fma2(unsigned long long& c, unsigned long long a, unsigned long long b) {
    asm("fma.rn.f32x2 %0, %1, %2, %3;" : "=l"(c) : "l"(a), "l"(b), "l"(c));
}
__device__ __forceinline__ float2 unpack2(unsigned long long v) {
    float2 f; asm("mov.b64 {%0,%1}, %2;" : "=f"(f.x), "=f"(f.y) : "l"(v)); return f;
}
__device__ __forceinline__ void split_bf(float x, __nv_bfloat16& h, __nv_bfloat16& l) {
    h = __float2bfloat16(x);
    l = __float2bfloat16(x - __bfloat162float(h));
}
__device__ __forceinline__ void mma_bf16(float* c, const uint32_t* a, const uint32_t* b) {
    asm("mma.sync.aligned.m16n8k16.row.col.f32.bf16.bf16.f32 "
        "{%0,%1,%2,%3},{%4,%5,%6,%7},{%8,%9},{%0,%1,%2,%3};"
        : "+f"(c[0]), "+f"(c[1]), "+f"(c[2]), "+f"(c[3])
        : "r"(a[0]), "r"(a[1]), "r"(a[2]), "r"(a[3]), "r"(b[0]), "r"(b[1]));
}

// ============ Stage 1: G[b] = K[b]^T @ V[b]  (bf16 split MMA, split-K) ============
__global__ void __launch_bounds__(256) k_g_mma(const float* __restrict__ keys,
                                               const float* __restrict__ values) {
    __shared__ __nv_bfloat16 sKh[DM][18], sKl[DM][18], sVh[DM][18], sVl[DM][18];
    const int sp = blockIdx.x, b = blockIdx.y;
    const int t = threadIdx.x, w = t >> 5, lane = t & 31;
    const int g = lane >> 2, tg = lane & 3;
    const float* Kb = keys   + ((size_t)b * NT + (size_t)sp * CH) * DM;
    const float* Vb = values + ((size_t)b * NT + (size_t)sp * CH) * DM;

    float acc[16][4];
#pragma unroll
    for (int i = 0; i < 16; i++) { acc[i][0]=acc[i][1]=acc[i][2]=acc[i][3]=0.f; }

    const int m4 = (t & 31) << 2, tr = t >> 5;  // each thread: dm cols m4..m4+3, tokens tr & tr+8
    float4 pk0 = *(const float4*)(Kb + (size_t)tr * DM + m4);
    float4 pk1 = *(const float4*)(Kb + (size_t)(tr + 8) * DM + m4);
    float4 pv0 = *(const float4*)(Vb + (size_t)tr * DM + m4);
    float4 pv1 = *(const float4*)(Vb + (size_t)(tr + 8) * DM + m4);

    for (int ks = 0; ks < ITG; ks++) {
#pragma unroll
        for (int j = 0; j < 4; j++) {
            __nv_bfloat16 h, l;
            split_bf(((const float*)&pk0)[j], h, l); sKh[m4+j][tr]   = h; sKl[m4+j][tr]   = l;
            split_bf(((const float*)&pk1)[j], h, l); sKh[m4+j][tr+8] = h; sKl[m4+j][tr+8] = l;
            split_bf(((const float*)&pv0)[j], h, l); sVh[m4+j][tr]   = h; sVl[m4+j][tr]   = l;
            split_bf(((const float*)&pv1)[j], h, l); sVh[m4+j][tr+8] = h; sVl[m4+j][tr+8] = l;
        }
        __syncthreads();
        if (ks + 1 < ITG) {  // prefetch next tile (overlaps with MMA below)
            const float* Kn = Kb + (size_t)(ks + 1) * 16 * DM;
            const float* Vn = Vb + (size_t)(ks + 1) * 16 * DM;
            pk0 = *(const float4*)(Kn + (size_t)tr * DM + m4);
            pk1 = *(const float4*)(Kn + (size_t)(tr + 8) * DM + m4);
            pv0 = *(const float4*)(Vn + (size_t)tr * DM + m4);
            pv1 = *(const float4*)(Vn + (size_t)(tr + 8) * DM + m4);
        }
        const int m = w * 16 + g;
        uint32_t ah[4], al[4];
        ah[0] = *(const uint32_t*)&sKh[m][2*tg];       ah[1] = *(const uint32_t*)&sKh[m+8][2*tg];
        ah[2] = *(const uint32_t*)&sKh[m][2*tg+8];     ah[3] = *(const uint32_t*)&sKh[m+8][2*tg+8];
        al[0] = *(const uint32_t*)&sKl[m][2*tg];       al[1] = *(const uint32_t*)&sKl[m+8][2*tg];
        al[2] = *(const uint32_t*)&sKl[m][2*tg+8];     al[3] = *(const uint32_t*)&sKl[m+8][2*tg+8];
#pragma unroll
        for (int j = 0; j < 16; j++) {
            const int n = j * 8 + g;
            uint32_t bh[2], bl[2];
            bh[0] = *(const uint32_t*)&sVh[n][2*tg];   bh[1] = *(const uint32_t*)&sVh[n][2*tg+8];
            bl[0] = *(const uint32_t*)&sVl[n][2*tg];   bl[1] = *(const uint32_t*)&sVl[n][2*tg+8];
            mma_bf16(acc[j], ah, bh);
            mma_bf16(acc[j], ah, bl);
            mma_bf16(acc[j], al, bh);
        }
        __syncthreads();
    }
    float* C = g_part + (size_t)(sp * B_ + b) * (DM * DM);
    const int m = w * 16 + g;
#pragma unroll
    for (int j = 0; j < 16; j++) {
        const int n = j * 8 + 2 * tg;
        *(float2*)(C + (size_t)m * DM + n)       = make_float2(acc[j][0], acc[j][1]);
        *(float2*)(C + (size_t)(m + 8) * DM + n) = make_float2(acc[j][2], acc[j][3]);
    }
}

__global__ void __launch_bounds__(256) k_reduce_G() {
    const int i = blockIdx.x * 256 + threadIdx.x;  // 65536
    const int b = i >> 14, e = i & 16383;
    float s = 0.f;
#pragma unroll 8
    for (int sp = 0; sp < SPG; sp++) s += g_part[(size_t)(sp * B_ + b) * 16384 + e];
    g_G[i] = s;
}

// ============ fp32 fma2 64x64 tile (glue) — staging buffers passed in ============
template <bool TA, bool TB>
__device__ __forceinline__ void gemm_tile(const float* __restrict__ A, const float* __restrict__ B,
                                          float* __restrict__ C, int K, int lda, int ldb, int ldc,
                                          float (*sA)[68], float (*sB)[68]) {
    const int t = threadIdx.x, tx = t & 15, ty = t >> 4;
    unsigned long long acc[4][2];
#pragma unroll
    for (int i = 0; i < 4; i++) { acc[i][0] = 0ULL; acc[i][1] = 0ULL; }
    for (int k0 = 0; k0 < K; k0 += 16) {
        if (TA) {
            const int kk = t >> 4, m4 = (t & 15) << 2;
            float4 v = *(const float4*)(A + (size_t)(k0 + kk) * lda + m4);
            *(float4*)&sA[kk][m4] = v;
        } else {
            const int m = t >> 2, k4 = (t & 3) << 2;
            float4 v = *(const float4*)(A + (size_t)m * lda + k0 + k4);
            sA[k4+0][m] = v.x; sA[k4+1][m] = v.y; sA[k4+2][m] = v.z; sA[k4+3][m] = v.w;
        }
        if (!TB) {
            const int kk = t >> 4, n4 = (t & 15) << 2;
            float4 v = *(const float4*)(B + (size_t)(k0 + kk) * ldb + n4);
            *(float4*)&sB[kk][n4] = v;
        } else {
            const int n = t >> 2, k4 = (t & 3) << 2;
            float4 v = *(const float4*)(B + (size_t)n * ldb + k0 + k4);
            sB[k4+0][n] = v.x; sB[k4+1][n] = v.y; sB[k4+2][n] = v.z; sB[k4+3][n] = v.w;
        }
        __syncthreads();
#pragma unroll
        for (int kk = 0; kk < 16; kk++) {
            const float4 a = *(const float4*)&sA[kk][ty << 2];
            const ulonglong2 bb = *(const ulonglong2*)&sB[kk][tx << 2];
            unsigned long long a0 = pack2(a.x, a.x), a1 = pack2(a.y, a.y);
            unsigned long long a2 = pack2(a.z, a.z), a3 = pack2(a.w, a.w);
            fma2(acc[0][0], a0, bb.x); fma2(acc[0][1], a0, bb.y);
            fma2(acc[1][0], a1, bb.x); fma2(acc[1][1], a1, bb.y);
            fma2(acc[2][0], a2, bb.x); fma2(acc[2][1], a2, bb.y);
            fma2(acc[3][0], a3, bb.x); fma2(acc[3][1], a3, bb.y);
        }
        __syncthreads();
    }
#pragma unroll
    for (int i = 0; i < 4; i++) {
        float2 lo = unpack2(acc[i][0]), hi = unpack2(acc[i][1]);
        float4 r = make_float4(lo.x, lo.y, hi.x, hi.y);
        *(float4*)(C + (size_t)((ty << 2) + i) * ldc + (tx << 2)) = r;
    }
}

// ============ Glue: per (b,h) chain  Wfin_h = Wq_h^T (Wk_h G Wk_h^T) Wo_h^T ============
__global__ void __launch_bounds__(256) k_glue(const float* __restrict__ Wq,
                                              const float* __restrict__ Wk,
                                              const float* __restrict__ Wo) {
    __shared__ float sA[16][68], sB[16][68];
    __shared__ float T2[64 * 64];
    const int z = blockIdx.x, b = z & 3, h = z >> 2;
    const float* Wkh = Wk + (size_t)h * 64 * DM;
    const float* Wqh = Wq + (size_t)h * 64 * DM;
    const float* Gb  = g_G + (size_t)b * DM * DM;
    float* T1 = g_T1 + (size_t)z * 64 * DM;
    float* T3 = g_T3 + (size_t)z * DM * 64;
    float* P  = g_part + (size_t)z * DM * DM;

    gemm_tile<false, false>(Wkh, Gb,      T1,      DM, DM, DM, DM, sA, sB);
    gemm_tile<false, false>(Wkh, Gb + 64, T1 + 64, DM, DM, DM, DM, sA, sB);
    __syncthreads();
    gemm_tile<false, true>(T1, Wkh, T2, DM, DM, DM, 64, sA, sB);
    __syncthreads();
    gemm_tile<true, false>(Wqh,      T2, T3,           64, DM, 64, 64, sA, sB);
    gemm_tile<true, false>(Wqh + 64, T2, T3 + 64 * 64, 64, DM, 64, 64, sA, sB);
    __syncthreads();
#pragma unroll
    for (int m0 = 0; m0 < 128; m0 += 64)
#pragma unroll
        for (int n0 = 0; n0 < 128; n0 += 64)
            gemm_tile<false, true>(T3 + (size_t)m0 * 64, Wo + (size_t)n0 * 512 + h * 64,
                                   P + (size_t)m0 * DM + n0, 64, 64, 512, DM, sA, sB);
}

__global__ void __launch_bounds__(256) k_reduce_F() {
    const int i = blockIdx.x * 256 + threadIdx.x;  // 65536
    float s = 0.f;
#pragma unroll
    for (int z = 0; z < 32; z += 4) s += g_part[(size_t)z * 16384 + i];  // z = h*4 + b, b fixed by i? no:
    // NOTE: layout is g_part[z = h*4 + b][k][n]; for output index i = b*16384 + e we must sum h.
    g_Wfin[i] = 0.f;  // overwritten below
    const int b = i >> 14, e = i & 16383;
    s = 0.f;
#pragma unroll
    for (int hh = 0; hh < 8; hh++) s += g_part[(size_t)(hh * 4 + b) * 16384 + e];
    g_Wfin[i] = s * (1.0f / (float)NT);
}

// ============ Stage 6: out[b] = Q[b] @ Wfin[b] + bo  (bf16 split MMA) ============
__global__ void __launch_bounds__(256, 2) k_out_mma(const float* __restrict__ q,
                                                    const float* __restrict__ bo,
                                                    float* __restrict__ out) {
    __shared__ __nv_bfloat16 sWh[64][130], sWl[64][130];  // [n][k], n-half per CTA
    __shared__ __nv_bfloat16 sQh[DM][18], sQl[DM][18];    // [token][k16]
    const int t = threadIdx.x, w = t >> 5, lane = t & 31;
    const int g = lane >> 2, tg = lane & 3;
    const int n0 = blockIdx.y * 64, b = blockIdx.z;
    const float* Wf = g_Wfin + (size_t)b * DM * DM;
    const float* Qb = q + (size_t)b * NT * DM;
    float* Ob = out + (size_t)b * NT * DM;

    // load Wfin^T half into smem (hi/lo)
    for (int i = t; i < 64 * 128; i += 256) {
        const int n = i & 63, k = i >> 6;
        __nv_bfloat16 h, l;
        split_bf(Wf[(size_t)k * DM + n0 + n], h, l);
        sWh[n][k] = h; sWl[n][k] = l;
    }
    __syncthreads();

    const int tok = t >> 2, kq = t & 3;  // Q load map: tokens tok, tok+64; float4 col kq
    for (int bl = 0; bl < 2; bl++) {
        const size_t tok0 = ((size_t)blockIdx.x * 2 + bl) * 128;
        float4 p0 = *(const float4*)(Qb + (tok0 + tok) * DM + kq * 4);
        float4 p1 = *(const float4*)(Qb + (tok0 + tok + 64) * DM + kq * 4);
        float acc[8][4];
#pragma unroll
        for (int i = 0; i < 8; i++) { acc[i][0]=acc[i][1]=acc[i][2]=acc[i][3]=0.f; }

        for (int ks = 0; ks < 8; ks++) {
#pragma unroll
            for (int j = 0; j < 4; j++) {
                __nv_bfloat16 h, l;
                split_bf(((const float*)&p0)[j], h, l); sQh[tok][kq*4+j]    = h; sQl[tok][kq*4+j]    = l;
                split_bf(((const float*)&p1)[j], h, l); sQh[tok+64][kq*4+j] = h; sQl[tok+64][kq*4+j] = l;
            }
            __syncthreads();
            if (ks + 1 < 8) {
                p0 = *(const float4*)(Qb + (tok0 + tok) * DM + (ks + 1) * 16 + kq * 4);
                p1 = *(const float4*)(Qb + (tok0 + tok + 64) * DM + (ks + 1) * 16 + kq * 4);
            } else if (bl == 0) {
                p0 = *(const float4*)(Qb + (tok0 + 128 + tok) * DM + kq * 4);
                p1 = *(const float4*)(Qb + (tok0 + 128 + tok + 64) * DM + kq * 4);
            }
            const int m = w * 16 + g;
            uint32_t ah[4], al[4];
            ah[0] = *(const uint32_t*)&sQh[m][2*tg];     ah[1] = *(const uint32_t*)&sQh[m+8][2*tg];
            ah[2] = *(const uint32_t*)&sQh[m][2*tg+8];   ah[3] = *(const uint32_t*)&sQh[m+8][2*tg+8];
            al[0] = *(const uint32_t*)&sQl[m][2*tg];     al[1] = *(const uint32_t*)&sQl[m+8][2*tg];
            al[2] = *(const uint32_t*)&sQl[m][2*tg+8];   al[3] = *(const uint32_t*)&sQl[m+8][2*tg+8];
#pragma unroll
            for (int j = 0; j < 8; j++) {
                const int n = j * 8 + g, kb = ks * 16;
                uint32_t bh[2], bl2[2];
                bh[0]  = *(const uint32_t*)&sWh[n][kb + 2*tg];  bh[1]  = *(const uint32_t*)&sWh[n][kb + 2*tg + 8];
                bl2[0] = *(const uint32_t*)&sWl[n][kb + 2*tg];  bl2[1] = *(const uint32_t*)&sWl[n][kb + 2*tg + 8];
                mma_bf16(acc[j], ah, bh);
                mma_bf16(acc[j], ah, bl2);
                mma_bf16(acc[j], al, bh);
            }
            __syncthreads();
        }
        const int m = w * 16 + g;
#pragma unroll
        for (int j = 0; j < 8; j++) {
            const int n = n0 + j * 8 + 2 * tg;
            const float2 bv = *(const float2*)(bo + n);
            *(float2*)(Ob + (tok0 + m) * DM + n)     = make_float2(acc[j][0] + bv.x, acc[j][1] + bv.y);
            *(float2*)(Ob + (tok0 + m + 8) * DM + n) = make_float2(acc[j][2] + bv.x, acc[j][3] + bv.y);
        }
    }
}

extern "C" void kernel_launch(void* const* d_in, const int* in_sizes, int n_in,
                              void* d_out, int out_size) {
    const float* queries = (const float*)d_in[0];
    const float* keys    = (const float*)d_in[1];
    const float* values  = (const float*)d_in[2];
    const float* Wq      = (const float*)d_in[3];
    const float* Wk      = (const float*)d_in[4];
    const float* Wo      = (const float*)d_in[5];
    const float* bo      = (const float*)d_in[6];
    float* out = (float*)d_out;

    k_g_mma   <<<dim3(SPG, B_), 256>>>(keys, values);
    k_reduce_G<<<256, 256>>>();
    k_glue    <<<32, 256>>>(Wq, Wk, Wo);
    k_reduce_F<<<256, 256>>>();
    k_out_mma <<<dim3(NT / 256, 2, B_), 256>>>(queries, bo, out);
}

// round 4
// speedup vs baseline: 1.0065x; 1.0065x over previous
#include <cuda_runtime.h>
#include <cuda_bf16.h>
#include <cstdint>
#include <cstddef>

#define B_ 4
#define NT 16384
#define DM 128
#define SPG 32
#define CH (NT / SPG)      // 512 tokens per G-split CTA
#define ITG (CH / 16)      // 32 k-steps

// Scratch (__device__ globals). g_part: G partials [32][4][128][128], reused as
// Wfin h-partials [8*4][128][128].
static __device__ float g_part[SPG * B_ * DM * DM];
static __device__ float g_G   [B_ * DM * DM];
static __device__ float g_T1  [32 * 64 * DM];
static __device__ float g_T3  [32 * DM * 64];
static __device__ float g_Wfin[B_ * DM * DM];

// ---------------- helpers ----------------
__device__ __forceinline__ unsigned long long pack2(float x, float y) {
    unsigned long long r; asm("mov.b64 %0, {%1,%2};" : "=l"(r) : "f"(x), "f"(y)); return r;
}
__device__ __forceinline__ void fma2(unsigned long long& c, unsigned long long a, unsigned long long b) {
    asm("fma.rn.f32x2 %0, %1, %2, %3;" : "=l"(c) : "l"(a), "l"(b), "l"(c));
}
__device__ __forceinline__ float2 unpack2(unsigned long long v) {
    float2 f; asm("mov.b64 {%0,%1}, %2;" : "=f"(f.x), "=f"(f.y) : "l"(v)); return f;
}
__device__ __forceinline__ void split_bf(float x, __nv_bfloat16& h, __nv_bfloat16& l) {
    h = __float2bfloat16(x);
    l = __float2bfloat16(x - __bfloat162float(h));
}
__device__ __forceinline__ void mma_bf16(float* c, const uint32_t* a, const uint32_t* b) {
    asm("mma.sync.aligned.m16n8k16.row.col.f32.bf16.bf16.f32 "
        "{%0,%1,%2,%3},{%4,%5,%6,%7},{%8,%9},{%0,%1,%2,%3};"
        : "+f"(c[0]), "+f"(c[1]), "+f"(c[2]), "+f"(c[3])
        : "r"(a[0]), "r"(a[1]), "r"(a[2]), "r"(a[3]), "r"(b[0]), "r"(b[1]));
}

// ============ Stage 1: G[b] = K[b]^T @ V[b]  (bf16 split MMA, split-K) ============
__global__ void __launch_bounds__(256) k_g_mma(const float* __restrict__ keys,
                                               const float* __restrict__ values) {
    __shared__ __nv_bfloat16 sKh[DM][18], sKl[DM][18], sVh[DM][18], sVl[DM][18];
    const int sp = blockIdx.x, b = blockIdx.y;
    const int t = threadIdx.x, w = t >> 5, lane = t & 31;
    const int g = lane >> 2, tg = lane & 3;
    const float* Kb = keys   + ((size_t)b * NT + (size_t)sp * CH) * DM;
    const float* Vb = values + ((size_t)b * NT + (size_t)sp * CH) * DM;

    float acc[16][4];
#pragma unroll
    for (int i = 0; i < 16; i++) { acc[i][0]=acc[i][1]=acc[i][2]=acc[i][3]=0.f; }

    const int m4 = (t & 31) << 2, tr = t >> 5;  // each thread: dm cols m4..m4+3, tokens tr & tr+8
    float4 pk0 = *(const float4*)(Kb + (size_t)tr * DM + m4);
    float4 pk1 = *(const float4*)(Kb + (size_t)(tr + 8) * DM + m4);
    float4 pv0 = *(const float4*)(Vb + (size_t)tr * DM + m4);
    float4 pv1 = *(const float4*)(Vb + (size_t)(tr + 8) * DM + m4);

    for (int ks = 0; ks < ITG; ks++) {
#pragma unroll
        for (int j = 0; j < 4; j++) {
            __nv_bfloat16 h, l;
            split_bf(((const float*)&pk0)[j], h, l); sKh[m4+j][tr]   = h; sKl[m4+j][tr]   = l;
            split_bf(((const float*)&pk1)[j], h, l); sKh[m4+j][tr+8] = h; sKl[m4+j][tr+8] = l;
            split_bf(((const float*)&pv0)[j], h, l); sVh[m4+j][tr]   = h; sVl[m4+j][tr]   = l;
            split_bf(((const float*)&pv1)[j], h, l); sVh[m4+j][tr+8] = h; sVl[m4+j][tr+8] = l;
        }
        __syncthreads();
        if (ks + 1 < ITG) {  // prefetch next tile (overlaps with MMA below)
            const float* Kn = Kb + (size_t)(ks + 1) * 16 * DM;
            const float* Vn = Vb + (size_t)(ks + 1) * 16 * DM;
            pk0 = *(const float4*)(Kn + (size_t)tr * DM + m4);
            pk1 = *(const float4*)(Kn + (size_t)(tr + 8) * DM + m4);
            pv0 = *(const float4*)(Vn + (size_t)tr * DM + m4);
            pv1 = *(const float4*)(Vn + (size_t)(tr + 8) * DM + m4);
        }
        const int m = w * 16 + g;
        uint32_t ah[4], al[4];
        ah[0] = *(const uint32_t*)&sKh[m][2*tg];       ah[1] = *(const uint32_t*)&sKh[m+8][2*tg];
        ah[2] = *(const uint32_t*)&sKh[m][2*tg+8];     ah[3] = *(const uint32_t*)&sKh[m+8][2*tg+8];
        al[0] = *(const uint32_t*)&sKl[m][2*tg];       al[1] = *(const uint32_t*)&sKl[m+8][2*tg];
        al[2] = *(const uint32_t*)&sKl[m][2*tg+8];     al[3] = *(const uint32_t*)&sKl[m+8][2*tg+8];
#pragma unroll
        for (int j = 0; j < 16; j++) {
            const int n = j * 8 + g;
            uint32_t bh[2], bl[2];
            bh[0] = *(const uint32_t*)&sVh[n][2*tg];   bh[1] = *(const uint32_t*)&sVh[n][2*tg+8];
            bl[0] = *(const uint32_t*)&sVl[n][2*tg];   bl[1] = *(const uint32_t*)&sVl[n][2*tg+8];
            mma_bf16(acc[j], ah, bh);
            mma_bf16(acc[j], ah, bl);
            mma_bf16(acc[j], al, bh);
        }
        __syncthreads();
    }
    float* C = g_part + (size_t)(sp * B_ + b) * (DM * DM);
    const int m = w * 16 + g;
#pragma unroll
    for (int j = 0; j < 16; j++) {
        const int n = j * 8 + 2 * tg;
        *(float2*)(C + (size_t)m * DM + n)       = make_float2(acc[j][0], acc[j][1]);
        *(float2*)(C + (size_t)(m + 8) * DM + n) = make_float2(acc[j][2], acc[j][3]);
    }
}

__global__ void __launch_bounds__(256) k_reduce_G() {
    const int i = blockIdx.x * 256 + threadIdx.x;  // 65536
    const int b = i >> 14, e = i & 16383;
    float s = 0.f;
#pragma unroll 8
    for (int sp = 0; sp < SPG; sp++) s += g_part[(size_t)(sp * B_ + b) * 16384 + e];
    g_G[i] = s;
}

// ============ fp32 fma2 64x64 tile (glue) — staging buffers passed in ============
template <bool TA, bool TB>
__device__ __forceinline__ void gemm_tile(const float* __restrict__ A, const float* __restrict__ B,
                                          float* __restrict__ C, int K, int lda, int ldb, int ldc,
                                          float (*sA)[68], float (*sB)[68]) {
    const int t = threadIdx.x, tx = t & 15, ty = t >> 4;
    unsigned long long acc[4][2];
#pragma unroll
    for (int i = 0; i < 4; i++) { acc[i][0] = 0ULL; acc[i][1] = 0ULL; }
    for (int k0 = 0; k0 < K; k0 += 16) {
        if (TA) {
            const int kk = t >> 4, m4 = (t & 15) << 2;
            float4 v = *(const float4*)(A + (size_t)(k0 + kk) * lda + m4);
            *(float4*)&sA[kk][m4] = v;
        } else {
            const int m = t >> 2, k4 = (t & 3) << 2;
            float4 v = *(const float4*)(A + (size_t)m * lda + k0 + k4);
            sA[k4+0][m] = v.x; sA[k4+1][m] = v.y; sA[k4+2][m] = v.z; sA[k4+3][m] = v.w;
        }
        if (!TB) {
            const int kk = t >> 4, n4 = (t & 15) << 2;
            float4 v = *(const float4*)(B + (size_t)(k0 + kk) * ldb + n4);
            *(float4*)&sB[kk][n4] = v;
        } else {
            const int n = t >> 2, k4 = (t & 3) << 2;
            float4 v = *(const float4*)(B + (size_t)n * ldb + k0 + k4);
            sB[k4+0][n] = v.x; sB[k4+1][n] = v.y; sB[k4+2][n] = v.z; sB[k4+3][n] = v.w;
        }
        __syncthreads();
#pragma unroll
        for (int kk = 0; kk < 16; kk++) {
            const float4 a = *(const float4*)&sA[kk][ty << 2];
            const ulonglong2 bb = *(const ulonglong2*)&sB[kk][tx << 2];
            unsigned long long a0 = pack2(a.x, a.x), a1 = pack2(a.y, a.y);
            unsigned long long a2 = pack2(a.z, a.z), a3 = pack2(a.w, a.w);
            fma2(acc[0][0], a0, bb.x); fma2(acc[0][1], a0, bb.y);
            fma2(acc[1][0], a1, bb.x); fma2(acc[1][1], a1, bb.y);
            fma2(acc[2][0], a2, bb.x); fma2(acc[2][1], a2, bb.y);
            fma2(acc[3][0], a3, bb.x); fma2(acc[3][1], a3, bb.y);
        }
        __syncthreads();
    }
#pragma unroll
    for (int i = 0; i < 4; i++) {
        float2 lo = unpack2(acc[i][0]), hi = unpack2(acc[i][1]);
        float4 r = make_float4(lo.x, lo.y, hi.x, hi.y);
        *(float4*)(C + (size_t)((ty << 2) + i) * ldc + (tx << 2)) = r;
    }
}

// ============ Glue: per (b,h) chain  Wfin_h = Wq_h^T (Wk_h G Wk_h^T) Wo_h^T ============
__global__ void __launch_bounds__(256) k_glue(const float* __restrict__ Wq,
                                              const float* __restrict__ Wk,
                                              const float* __restrict__ Wo) {
    __shared__ float sA[16][68], sB[16][68];
    __shared__ float T2[64 * 64];
    const int z = blockIdx.x, b = z & 3, h = z >> 2;
    const float* Wkh = Wk + (size_t)h * 64 * DM;
    const float* Wqh = Wq + (size_t)h * 64 * DM;
    const float* Gb  = g_G + (size_t)b * DM * DM;
    float* T1 = g_T1 + (size_t)z * 64 * DM;
    float* T3 = g_T3 + (size_t)z * DM * 64;
    float* P  = g_part + (size_t)z * DM * DM;

    gemm_tile<false, false>(Wkh, Gb,      T1,      DM, DM, DM, DM, sA, sB);
    gemm_tile<false, false>(Wkh, Gb + 64, T1 + 64, DM, DM, DM, DM, sA, sB);
    __syncthreads();
    gemm_tile<false, true>(T1, Wkh, T2, DM, DM, DM, 64, sA, sB);
    __syncthreads();
    gemm_tile<true, false>(Wqh,      T2, T3,           64, DM, 64, 64, sA, sB);
    gemm_tile<true, false>(Wqh + 64, T2, T3 + 64 * 64, 64, DM, 64, 64, sA, sB);
    __syncthreads();
#pragma unroll
    for (int m0 = 0; m0 < 128; m0 += 64)
#pragma unroll
        for (int n0 = 0; n0 < 128; n0 += 64)
            gemm_tile<false, true>(T3 + (size_t)m0 * 64, Wo + (size_t)n0 * 512 + h * 64,
                                   P + (size_t)m0 * DM + n0, 64, 64, 512, DM, sA, sB);
}

__global__ void __launch_bounds__(256) k_reduce_F() {
    const int i = blockIdx.x * 256 + threadIdx.x;  // 65536
    float s = 0.f;
#pragma unroll
    for (int z = 0; z < 32; z += 4) s += g_part[(size_t)z * 16384 + i];  // z = h*4 + b, b fixed by i? no:
    // NOTE: layout is g_part[z = h*4 + b][k][n]; for output index i = b*16384 + e we must sum h.
    g_Wfin[i] = 0.f;  // overwritten below
    const int b = i >> 14, e = i & 16383;
    s = 0.f;
#pragma unroll
    for (int hh = 0; hh < 8; hh++) s += g_part[(size_t)(hh * 4 + b) * 16384 + e];
    g_Wfin[i] = s * (1.0f / (float)NT);
}

// ============ Stage 6: out[b] = Q[b] @ Wfin[b] + bo  (bf16 split MMA) ============
__global__ void __launch_bounds__(256, 2) k_out_mma(const float* __restrict__ q,
                                                    const float* __restrict__ bo,
                                                    float* __restrict__ out) {
    __shared__ __nv_bfloat16 sWh[64][130], sWl[64][130];  // [n][k], n-half per CTA
    __shared__ __nv_bfloat16 sQh[DM][18], sQl[DM][18];    // [token][k16]
    const int t = threadIdx.x, w = t >> 5, lane = t & 31;
    const int g = lane >> 2, tg = lane & 3;
    const int n0 = blockIdx.y * 64, b = blockIdx.z;
    const float* Wf = g_Wfin + (size_t)b * DM * DM;
    const float* Qb = q + (size_t)b * NT * DM;
    float* Ob = out + (size_t)b * NT * DM;

    // load Wfin^T half into smem (hi/lo)
    for (int i = t; i < 64 * 128; i += 256) {
        const int n = i & 63, k = i >> 6;
        __nv_bfloat16 h, l;
        split_bf(Wf[(size_t)k * DM + n0 + n], h, l);
        sWh[n][k] = h; sWl[n][k] = l;
    }
    __syncthreads();

    const int tok = t >> 2, kq = t & 3;  // Q load map: tokens tok, tok+64; float4 col kq
    for (int bl = 0; bl < 2; bl++) {
        const size_t tok0 = ((size_t)blockIdx.x * 2 + bl) * 128;
        float4 p0 = *(const float4*)(Qb + (tok0 + tok) * DM + kq * 4);
        float4 p1 = *(const float4*)(Qb + (tok0 + tok + 64) * DM + kq * 4);
        float acc[8][4];
#pragma unroll
        for (int i = 0; i < 8; i++) { acc[i][0]=acc[i][1]=acc[i][2]=acc[i][3]=0.f; }

        for (int ks = 0; ks < 8; ks++) {
#pragma unroll
            for (int j = 0; j < 4; j++) {
                __nv_bfloat16 h, l;
                split_bf(((const float*)&p0)[j], h, l); sQh[tok][kq*4+j]    = h; sQl[tok][kq*4+j]    = l;
                split_bf(((const float*)&p1)[j], h, l); sQh[tok+64][kq*4+j] = h; sQl[tok+64][kq*4+j] = l;
            }
            __syncthreads();
            if (ks + 1 < 8) {
                p0 = *(const float4*)(Qb + (tok0 + tok) * DM + (ks + 1) * 16 + kq * 4);
                p1 = *(const float4*)(Qb + (tok0 + tok + 64) * DM + (ks + 1) * 16 + kq * 4);
            } else if (bl == 0) {
                p0 = *(const float4*)(Qb + (tok0 + 128 + tok) * DM + kq * 4);
                p1 = *(const float4*)(Qb + (tok0 + 128 + tok + 64) * DM + kq * 4);
            }
            const int m = w * 16 + g;
            uint32_t ah[4], al[4];
            ah[0] = *(const uint32_t*)&sQh[m][2*tg];     ah[1] = *(const uint32_t*)&sQh[m+8][2*tg];
            ah[2] = *(const uint32_t*)&sQh[m][2*tg+8];   ah[3] = *(const uint32_t*)&sQh[m+8][2*tg+8];
            al[0] = *(const uint32_t*)&sQl[m][2*tg];     al[1] = *(const uint32_t*)&sQl[m+8][2*tg];
            al[2] = *(const uint32_t*)&sQl[m][2*tg+8];   al[3] = *(const uint32_t*)&sQl[m+8][2*tg+8];
#pragma unroll
            for (int j = 0; j < 8; j++) {
                const int n = j * 8 + g, kb = ks * 16;
                uint32_t bh[2], bl2[2];
                bh[0]  = *(const uint32_t*)&sWh[n][kb + 2*tg];  bh[1]  = *(const uint32_t*)&sWh[n][kb + 2*tg + 8];
                bl2[0] = *(const uint32_t*)&sWl[n][kb + 2*tg];  bl2[1] = *(const uint32_t*)&sWl[n][kb + 2*tg + 8];
                mma_bf16(acc[j], ah, bh);
                mma_bf16(acc[j], ah, bl2);
                mma_bf16(acc[j], al, bh);
            }
            __syncthreads();
        }
        const int m = w * 16 + g;
#pragma unroll
        for (int j = 0; j < 8; j++) {
            const int n = n0 + j * 8 + 2 * tg;
            const float2 bv = *(const float2*)(bo + n);
            *(float2*)(Ob + (tok0 + m) * DM + n)     = make_float2(acc[j][0] + bv.x, acc[j][1] + bv.y);
            *(float2*)(Ob + (tok0 + m + 8) * DM + n) = make_float2(acc[j][2] + bv.x, acc[j][3] + bv.y);
        }
    }
}

extern "C" void kernel_launch(void* const* d_in, const int* in_sizes, int n_in,
                              void* d_out, int out_size) {
    const float* queries = (const float*)d_in[0];
    const float* keys    = (const float*)d_in[1];
    const float* values  = (const float*)d_in[2];
    const float* Wq      = (const float*)d_in[3];
    const float* Wk      = (const float*)d_in[4];
    const float* Wo      = (const float*)d_in[5];
    const float* bo      = (const float*)d_in[6];
    float* out = (float*)d_out;

    k_g_mma   <<<dim3(SPG, B_), 256>>>(keys, values);
    k_reduce_G<<<256, 256>>>();
    k_glue    <<<32, 256>>>(Wq, Wk, Wo);
    k_reduce_F<<<256, 256>>>();
    k_out_mma <<<dim3(NT / 256, 2, B_), 256>>>(queries, bo, out);
}

// round 8
// speedup vs baseline: 1.0360x; 1.0293x over previous
#include <cuda_runtime.h>
#include <cstdint>
#include <cstddef>

#define B_ 4
#define NT 16384
#define DM 128
#define SPG 37   // G splits per batch; 37*4 = 148 CTAs = one full wave

static __device__ float g_part[SPG * B_ * DM * DM];
static __device__ float g_G   [B_ * DM * DM];
static __device__ float g_Wfin[B_ * DM * DM];

// ---------- helpers ----------
__device__ __forceinline__ uint32_t smem_u32(const void* p) {
    uint32_t a;
    asm("{ .reg .u64 t; cvta.to.shared.u64 t, %1; cvt.u32.u64 %0, t; }" : "=r"(a) : "l"(p));
    return a;
}
__device__ __forceinline__ unsigned long long pk2(float x, float y) {
    unsigned long long r; asm("mov.b64 %0, {%1,%2};" : "=l"(r) : "f"(x), "f"(y)); return r;
}
__device__ __forceinline__ void fma2(unsigned long long& c, unsigned long long a, unsigned long long b) {
    asm("fma.rn.f32x2 %0, %1, %2, %3;" : "=l"(c) : "l"(a), "l"(b), "l"(c));
}
__device__ __forceinline__ float2 up2(unsigned long long v) {
    float2 f; asm("mov.b64 {%0,%1}, %2;" : "=f"(f.x), "=f"(f.y) : "l"(v)); return f;
}
__device__ __forceinline__ void cp16(uint32_t dst, const void* src) {
    asm volatile("cp.async.cg.shared.global [%0], [%1], 16;" :: "r"(dst), "l"(src) : "memory");
}
#define CP_COMMIT() asm volatile("cp.async.commit_group;" ::: "memory")
#define CP_WAIT0()  asm volatile("cp.async.wait_group 0;" ::: "memory")
#define CP_WAIT1()  asm volatile("cp.async.wait_group 1;" ::: "memory")

#define ROW4(AS, OFF) { const unsigned long long _a = pk2(AS, AS); \
    fma2(acc[(OFF)+0], _a, bb0.x); fma2(acc[(OFF)+1], _a, bb0.y); \
    fma2(acc[(OFF)+2], _a, bb1.x); fma2(acc[(OFF)+3], _a, bb1.y); }

// ============ G[b] = K[b]^T V[b], persistent, 148 CTAs ============
__global__ void __launch_bounds__(256) k_g(const float* __restrict__ keys,
                                           const float* __restrict__ values) {
    extern __shared__ float s[];            // sK[2][16][128], sV[2][16][128]
    float* sK = s;
    float* sV = s + 4096;
    const uint32_t sKa = smem_u32(sK), sVa = smem_u32(sV);
    const int t = threadIdx.x, tx = t & 15, ty = t >> 4;
    const int sp = blockIdx.x % SPG, b = blockIdx.x / SPG;
    const int c0 = (sp * 1024) / SPG, c1 = ((sp + 1) * 1024) / SPG;  // 16-token chunks
    const float* Kb = keys   + (size_t)b * NT * DM;
    const float* Vb = values + (size_t)b * NT * DM;

    unsigned long long acc[32] = {};

    auto issue = [&](int c, int buf) {
        const char* Kg = (const char*)(Kb + (size_t)c * 16 * DM);
        const char* Vg = (const char*)(Vb + (size_t)c * 16 * DM);
        const uint32_t dK = sKa + buf * 8192, dV = sVa + buf * 8192;
#pragma unroll
        for (int r = 0; r < 2; r++) {
            const int i = r * 256 + t;
            cp16(dK + i * 16, Kg + i * 16);
            cp16(dV + i * 16, Vg + i * 16);
        }
        CP_COMMIT();
    };
    issue(c0, 0);
    for (int c = c0; c < c1; c++) {
        const int li = c - c0;
        const bool more = (c + 1 < c1);
        if (more) issue(c + 1, (li + 1) & 1);
        if (more) CP_WAIT1(); else CP_WAIT0();
        __syncthreads();
        const float* bK = sK + (li & 1) * 2048;
        const float* bV = sV + (li & 1) * 2048;
#pragma unroll
        for (int kk = 0; kk < 16; kk++) {
            const float4 a0 = *(const float4*)(bK + kk * 128 + ty * 8);
            const float4 a1 = *(const float4*)(bK + kk * 128 + ty * 8 + 4);
            const ulonglong2 bb0 = *(const ulonglong2*)(bV + kk * 128 + tx * 8);
            const ulonglong2 bb1 = *(const ulonglong2*)(bV + kk * 128 + tx * 8 + 4);
            ROW4(a0.x, 0)  ROW4(a0.y, 4)  ROW4(a0.z, 8)  ROW4(a0.w, 12)
            ROW4(a1.x, 16) ROW4(a1.y, 20) ROW4(a1.z, 24) ROW4(a1.w, 28)
        }
        __syncthreads();
    }
    float* P = g_part + ((size_t)b * SPG + sp) * 16384;
#pragma unroll
    for (int i = 0; i < 8; i++) {
        float* row = P + (size_t)(ty * 8 + i) * 128 + tx * 8;
        ulonglong2 v0; v0.x = acc[i * 4]; v0.y = acc[i * 4 + 1];
        ulonglong2 v1; v1.x = acc[i * 4 + 2]; v1.y = acc[i * 4 + 3];
        *(ulonglong2*)row = v0;
        *(ulonglong2*)(row + 4) = v1;
    }
}

__global__ void __launch_bounds__(256) k_reduce_G() {
    const int i4 = blockIdx.x * 256 + threadIdx.x;  // 16384 float4s
    const int b = i4 >> 12, e4 = i4 & 4095;
    float4 s = make_float4(0, 0, 0, 0);
#pragma unroll
    for (int sp = 0; sp < SPG; sp++) {
        const float4 v = ((const float4*)g_part)[((size_t)b * SPG + sp) * 4096 + e4];
        s.x += v.x; s.y += v.y; s.z += v.z; s.w += v.w;
    }
    ((float4*)g_G)[i4] = s;
}

// ---------- fp32 fma2 64x64 tile (glue) ----------
template <bool TA, bool TB>
__device__ __forceinline__ void gemm_tile(const float* A, const float* B, float* C, int K,
                                          int lda, int ldb, int ldc, float (*sA)[68], float (*sB)[68]) {
    const int t = threadIdx.x, tx = t & 15, ty = t >> 4;
    unsigned long long acc[4][2] = {};
    for (int k0 = 0; k0 < K; k0 += 16) {
        if (TA) {
            const int kk = t >> 4, m4 = (t & 15) << 2;
            *(float4*)&sA[kk][m4] = *(const float4*)(A + (size_t)(k0 + kk) * lda + m4);
        } else {
            const int m = t >> 2, k4 = (t & 3) << 2;
            float4 v = *(const float4*)(A + (size_t)m * lda + k0 + k4);
            sA[k4][m] = v.x; sA[k4+1][m] = v.y; sA[k4+2][m] = v.z; sA[k4+3][m] = v.w;
        }
        if (!TB) {
            const int kk = t >> 4, n4 = (t & 15) << 2;
            *(float4*)&sB[kk][n4] = *(const float4*)(B + (size_t)(k0 + kk) * ldb + n4);
        } else {
            const int n = t >> 2, k4 = (t & 3) << 2;
            float4 v = *(const float4*)(B + (size_t)n * ldb + k0 + k4);
            sB[k4][n] = v.x; sB[k4+1][n] = v.y; sB[k4+2][n] = v.z; sB[k4+3][n] = v.w;
        }
        __syncthreads();
#pragma unroll
        for (int kk = 0; kk < 16; kk++) {
            const float4 a = *(const float4*)&sA[kk][ty << 2];
            const ulonglong2 bb = *(const ulonglong2*)&sB[kk][tx << 2];
            unsigned long long a0 = pk2(a.x, a.x), a1 = pk2(a.y, a.y), a2 = pk2(a.z, a.z), a3 = pk2(a.w, a.w);
            fma2(acc[0][0], a0, bb.x); fma2(acc[0][1], a0, bb.y);
            fma2(acc[1][0], a1, bb.x); fma2(acc[1][1], a1, bb.y);
            fma2(acc[2][0], a2, bb.x); fma2(acc[2][1], a2, bb.y);
            fma2(acc[3][0], a3, bb.x); fma2(acc[3][1], a3, bb.y);
        }
        __syncthreads();
    }
#pragma unroll
    for (int i = 0; i < 4; i++)
        *(ulonglong2*)(C + (size_t)((ty << 2) + i) * ldc + (tx << 2)) = *(ulonglong2*)acc[i];
}

// ============ Glue: Wfin partial per (b,h), SMEM-resident ============
__global__ void __launch_bounds__(256) k_glue(const float* __restrict__ Wq,
                                              const float* __restrict__ Wk,
                                              const float* __restrict__ Wo) {
    extern __shared__ float sf[];
    float* sG   = sf;            // 16384 (G, later T3)
    float* sWk  = sf + 16384;    // 8192
    float* sWx  = sf + 24576;    // 8192 (Wq then Wo)
    float* sT13 = sf + 32768;    // 8192 (T1)
    float* sT2  = sf + 40960;    // 4096
    float (*sA)[68] = (float(*)[68])(sf + 45056);
    float (*sB)[68] = (float(*)[68])(sf + 45056 + 16 * 68);
    const int t = threadIdx.x, z = blockIdx.x, b = z & 3, h = z >> 2;

    const float4* G4 = (const float4*)(g_G + (size_t)b * 16384);
    const float4* K4 = (const float4*)(Wk + (size_t)h * 64 * DM);
    const float4* Q4 = (const float4*)(Wq + (size_t)h * 64 * DM);
    for (int i = t; i < 4096; i += 256) ((float4*)sG)[i] = G4[i];
    for (int i = t; i < 2048; i += 256) { ((float4*)sWk)[i] = K4[i]; ((float4*)sWx)[i] = Q4[i]; }
    __syncthreads();
    gemm_tile<false, false>(sWk, sG,      sT13,      128, 128, 128, 128, sA, sB);
    gemm_tile<false, false>(sWk, sG + 64, sT13 + 64, 128, 128, 128, 128, sA, sB);
    __syncthreads();
    gemm_tile<false, true>(sT13, sWk, sT2, 128, 128, 128, 64, sA, sB);
    __syncthreads();
    gemm_tile<true, false>(sWx,      sT2, sG,           64, 128, 64, 64, sA, sB);  // T3 rows 0-63
    gemm_tile<true, false>(sWx + 64, sT2, sG + 64 * 64, 64, 128, 64, 64, sA, sB);  // T3 rows 64-127
    __syncthreads();
    for (int i = t; i < 8192; i += 256) sWx[i] = Wo[(size_t)(i >> 6) * 512 + h * 64 + (i & 63)];
    __syncthreads();
    float* P = g_part + (size_t)z * 16384;
#pragma unroll
    for (int m0 = 0; m0 < 128; m0 += 64)
#pragma unroll
        for (int n0 = 0; n0 < 128; n0 += 64)
            gemm_tile<false, true>(sG + m0 * 64, sWx + n0 * 64, P + (size_t)m0 * DM + n0,
                                   64, 64, 64, DM, sA, sB);
}

__global__ void __launch_bounds__(256) k_reduce_F() {
    const int i4 = blockIdx.x * 256 + threadIdx.x;  // MUST cover 16384 float4s (64 blocks)
    const int b = i4 >> 12, e4 = i4 & 4095;
    float4 s = make_float4(0, 0, 0, 0);
#pragma unroll
    for (int hh = 0; hh < 8; hh++) {
        const float4 v = ((const float4*)g_part)[(size_t)(hh * 4 + b) * 4096 + e4];
        s.x += v.x; s.y += v.y; s.z += v.z; s.w += v.w;
    }
    const float c = 1.0f / (float)NT;
    ((float4*)g_Wfin)[i4] = make_float4(s.x * c, s.y * c, s.z * c, s.w * c);
}

// ============ out = Q @ Wfin + bo, persistent, 148 CTAs ============
__global__ void __launch_bounds__(256) k_out(const float* __restrict__ q,
                                             const float* __restrict__ bo,
                                             float* __restrict__ out) {
    extern __shared__ float s[];
    float* sW = s;               // 16384 floats (Wfin of current batch)
    float* sQ = s + 16384;       // [2][128][128]
    __shared__ float sbo[128];
    const uint32_t sQa = smem_u32(sQ);
    const int t = threadIdx.x, tx = t & 15, ty = t >> 4;
    const int cta = blockIdx.x;
    const int c0 = (cta * 512) / 148, c1 = ((cta + 1) * 512) / 148;  // 128-token chunks
    if (t < 128) sbo[t] = bo[t];

    auto issueQ = [&](int c, int buf) {
        const char* src = (const char*)(q + ((size_t)(c >> 7) * NT + (size_t)(c & 127) * 128) * DM);
        const uint32_t dst = sQa + buf * 65536;
#pragma unroll
        for (int r = 0; r < 16; r++) {
            const int i = r * 256 + t;
            cp16(dst + i * 16, src + i * 16);
        }
        CP_COMMIT();
    };
    issueQ(c0, 0);
    int curb = -1;
    for (int c = c0; c < c1; c++) {
        const int li = c - c0;
        const bool more = (c + 1 < c1);
        if (more) issueQ(c + 1, (li + 1) & 1);
        const int bch = c >> 7;
        if (bch != curb) {
            __syncthreads();
            const float4* Wg = (const float4*)(g_Wfin + (size_t)bch * 16384);
#pragma unroll
            for (int r = 0; r < 16; r++) { const int i = r * 256 + t; ((float4*)sW)[i] = Wg[i]; }
            curb = bch;
        }
        if (more) CP_WAIT1(); else CP_WAIT0();
        __syncthreads();
        const float* bQ = sQ + (li & 1) * 16384;

        unsigned long long acc[32] = {};
#pragma unroll
        for (int kk = 0; kk < 128; kk++) {
            const ulonglong2 bb0 = *(const ulonglong2*)(sW + kk * 128 + tx * 8);
            const ulonglong2 bb1 = *(const ulonglong2*)(sW + kk * 128 + tx * 8 + 4);
            const float* qc = bQ + ty * 8 * 128 + kk;
            ROW4(qc[0], 0)       ROW4(qc[128], 4)     ROW4(qc[256], 8)     ROW4(qc[384], 12)
            ROW4(qc[512], 16)    ROW4(qc[640], 20)    ROW4(qc[768], 24)    ROW4(qc[896], 28)
        }
        const size_t tok0 = (size_t)(c & 127) * 128;
        float* Ob = out + ((size_t)bch * NT + tok0) * DM;
#pragma unroll
        for (int i = 0; i < 8; i++) {
            float* row = Ob + (size_t)(ty * 8 + i) * 128 + tx * 8;
            float2 v0 = up2(acc[i * 4]),     v1 = up2(acc[i * 4 + 1]);
            float2 v2 = up2(acc[i * 4 + 2]), v3 = up2(acc[i * 4 + 3]);
            const float4 b0 = *(const float4*)(sbo + tx * 8);
            const float4 b1 = *(const float4*)(sbo + tx * 8 + 4);
            *(float4*)row       = make_float4(v0.x + b0.x, v0.y + b0.y, v1.x + b0.z, v1.y + b0.w);
            *(float4*)(row + 4) = make_float4(v2.x + b1.x, v2.y + b1.y, v3.x + b1.z, v3.y + b1.w);
        }
        __syncthreads();
    }
}

extern "C" void kernel_launch(void* const* d_in, const int* in_sizes, int n_in,
                              void* d_out, int out_size) {
    const float* queries = (const float*)d_in[0];
    const float* keys    = (const float*)d_in[1];
    const float* values  = (const float*)d_in[2];
    const float* Wq      = (const float*)d_in[3];
    const float* Wk      = (const float*)d_in[4];
    const float* Wo      = (const float*)d_in[5];
    const float* bo      = (const float*)d_in[6];
    float* out = (float*)d_out;

    cudaFuncSetAttribute(k_glue, cudaFuncAttributeMaxDynamicSharedMemorySize, 188928);
    cudaFuncSetAttribute(k_out,  cudaFuncAttributeMaxDynamicSharedMemorySize, 196608);

    k_g       <<<148, 256, 32768>>>(keys, values);
    k_reduce_G<<<64, 256>>>();
    k_glue    <<<32, 256, 188928>>>(Wq, Wk, Wo);
    k_reduce_F<<<64, 256>>>();
    k_out     <<<148, 256, 196608>>>(queries, bo, out);
}

// round 9
// speedup vs baseline: 1.0498x; 1.0133x over previous
#include <cuda_runtime.h>
#include <cuda_bf16.h>
#include <cstdint>
#include <cstddef>

#define B_ 4
#define NT 16384
#define DM 128
#define SPG 74   // G splits per batch; 74*4 = 296 CTAs = 2/SM

static __device__ float g_part[SPG * B_ * DM * DM];
static __device__ float g_G   [B_ * DM * DM];
static __device__ float g_Wfin[B_ * DM * DM];

// ---------- helpers ----------
__device__ __forceinline__ unsigned long long pk2(float x, float y) {
    unsigned long long r; asm("mov.b64 %0, {%1,%2};" : "=l"(r) : "f"(x), "f"(y)); return r;
}
__device__ __forceinline__ void fma2(unsigned long long& c, unsigned long long a, unsigned long long b) {
    asm("fma.rn.f32x2 %0, %1, %2, %3;" : "=l"(c) : "l"(a), "l"(b), "l"(c));
}
__device__ __forceinline__ void split_bf(float x, __nv_bfloat16& h, __nv_bfloat16& l) {
    h = __float2bfloat16(x);
    l = __float2bfloat16(x - __bfloat162float(h));
}
__device__ __forceinline__ void mma_bf16(float* c, const uint32_t* a, const uint32_t* b) {
    asm("mma.sync.aligned.m16n8k16.row.col.f32.bf16.bf16.f32 "
        "{%0,%1,%2,%3},{%4,%5,%6,%7},{%8,%9},{%0,%1,%2,%3};"
        : "+f"(c[0]), "+f"(c[1]), "+f"(c[2]), "+f"(c[3])
        : "r"(a[0]), "r"(a[1]), "r"(a[2]), "r"(a[3]), "r"(b[0]), "r"(b[1]));
}

// ============ G[b] = K^T V, bf16 3-split mma, split-K, double-buffered ============
__global__ void __launch_bounds__(256, 2) k_g(const float* __restrict__ keys,
                                              const float* __restrict__ values) {
    __shared__ __nv_bfloat16 sKh[2][DM][18], sKl[2][DM][18], sVh[2][DM][18], sVl[2][DM][18];
    const int sp = blockIdx.x, b = blockIdx.y;
    const int t = threadIdx.x, w = t >> 5, lane = t & 31;
    const int g = lane >> 2, tg = lane & 3;
    const int c0 = (sp * 1024) / SPG, c1 = ((sp + 1) * 1024) / SPG;  // 16-token chunks
    const float* Kb = keys   + (size_t)b * NT * DM;
    const float* Vb = values + (size_t)b * NT * DM;

    float acc[16][4] = {};
    const int m4 = (t & 31) << 2, tr = t >> 5;
    const float* Kc = Kb + (size_t)c0 * 16 * DM;
    const float* Vc = Vb + (size_t)c0 * 16 * DM;
    float4 pk0 = *(const float4*)(Kc + (size_t)tr * DM + m4);
    float4 pk1 = *(const float4*)(Kc + (size_t)(tr + 8) * DM + m4);
    float4 pv0 = *(const float4*)(Vc + (size_t)tr * DM + m4);
    float4 pv1 = *(const float4*)(Vc + (size_t)(tr + 8) * DM + m4);

    for (int c = c0; c < c1; c++) {
        const int bf = (c - c0) & 1;
#pragma unroll
        for (int j = 0; j < 4; j++) {
            __nv_bfloat16 h, l;
            split_bf(((const float*)&pk0)[j], h, l); sKh[bf][m4+j][tr]   = h; sKl[bf][m4+j][tr]   = l;
            split_bf(((const float*)&pk1)[j], h, l); sKh[bf][m4+j][tr+8] = h; sKl[bf][m4+j][tr+8] = l;
            split_bf(((const float*)&pv0)[j], h, l); sVh[bf][m4+j][tr]   = h; sVl[bf][m4+j][tr]   = l;
            split_bf(((const float*)&pv1)[j], h, l); sVh[bf][m4+j][tr+8] = h; sVl[bf][m4+j][tr+8] = l;
        }
        __syncthreads();   // single bar: conv(i+1) goes to other buffer, overlaps mma(i)
        if (c + 1 < c1) {
            const float* Kn = Kb + (size_t)(c + 1) * 16 * DM;
            const float* Vn = Vb + (size_t)(c + 1) * 16 * DM;
            pk0 = *(const float4*)(Kn + (size_t)tr * DM + m4);
            pk1 = *(const float4*)(Kn + (size_t)(tr + 8) * DM + m4);
            pv0 = *(const float4*)(Vn + (size_t)tr * DM + m4);
            pv1 = *(const float4*)(Vn + (size_t)(tr + 8) * DM + m4);
        }
        const int m = w * 16 + g;
        uint32_t ah[4], al[4];
        ah[0] = *(const uint32_t*)&sKh[bf][m][2*tg];     ah[1] = *(const uint32_t*)&sKh[bf][m+8][2*tg];
        ah[2] = *(const uint32_t*)&sKh[bf][m][2*tg+8];   ah[3] = *(const uint32_t*)&sKh[bf][m+8][2*tg+8];
        al[0] = *(const uint32_t*)&sKl[bf][m][2*tg];     al[1] = *(const uint32_t*)&sKl[bf][m+8][2*tg];
        al[2] = *(const uint32_t*)&sKl[bf][m][2*tg+8];   al[3] = *(const uint32_t*)&sKl[bf][m+8][2*tg+8];
#pragma unroll
        for (int j = 0; j < 16; j++) {
            const int n = j * 8 + g;
            uint32_t bh[2], bl[2];
            bh[0] = *(const uint32_t*)&sVh[bf][n][2*tg]; bh[1] = *(const uint32_t*)&sVh[bf][n][2*tg+8];
            bl[0] = *(const uint32_t*)&sVl[bf][n][2*tg]; bl[1] = *(const uint32_t*)&sVl[bf][n][2*tg+8];
            mma_bf16(acc[j], ah, bh);
            mma_bf16(acc[j], ah, bl);
            mma_bf16(acc[j], al, bh);
        }
    }
    float* C = g_part + ((size_t)b * SPG + sp) * 16384;
    const int m = w * 16 + g;
#pragma unroll
    for (int j = 0; j < 16; j++) {
        const int n = j * 8 + 2 * tg;
        *(float2*)(C + (size_t)m * DM + n)       = make_float2(acc[j][0], acc[j][1]);
        *(float2*)(C + (size_t)(m + 8) * DM + n) = make_float2(acc[j][2], acc[j][3]);
    }
}

__global__ void __launch_bounds__(256) k_reduce_G() {
    const int i4 = blockIdx.x * 256 + threadIdx.x;  // 16384 float4s
    const int b = i4 >> 12, e4 = i4 & 4095;
    float4 s = make_float4(0, 0, 0, 0);
#pragma unroll
    for (int sp = 0; sp < SPG; sp++) {
        const float4 v = ((const float4*)g_part)[((size_t)b * SPG + sp) * 4096 + e4];
        s.x += v.x; s.y += v.y; s.z += v.z; s.w += v.w;
    }
    ((float4*)g_G)[i4] = s;
}

// ---------- fp32 fma2 64x64 tile (glue) ----------
template <bool TA, bool TB>
__device__ __forceinline__ void gemm_tile(const float* A, const float* B, float* C, int K,
                                          int lda, int ldb, int ldc, float (*sA)[68], float (*sB)[68]) {
    const int t = threadIdx.x, tx = t & 15, ty = t >> 4;
    unsigned long long acc[4][2] = {};
    for (int k0 = 0; k0 < K; k0 += 16) {
        if (TA) {
            const int kk = t >> 4, m4 = (t & 15) << 2;
            *(float4*)&sA[kk][m4] = *(const float4*)(A + (size_t)(k0 + kk) * lda + m4);
        } else {
            const int m = t >> 2, k4 = (t & 3) << 2;
            float4 v = *(const float4*)(A + (size_t)m * lda + k0 + k4);
            sA[k4][m] = v.x; sA[k4+1][m] = v.y; sA[k4+2][m] = v.z; sA[k4+3][m] = v.w;
        }
        if (!TB) {
            const int kk = t >> 4, n4 = (t & 15) << 2;
            *(float4*)&sB[kk][n4] = *(const float4*)(B + (size_t)(k0 + kk) * ldb + n4);
        } else {
            const int n = t >> 2, k4 = (t & 3) << 2;
            float4 v = *(const float4*)(B + (size_t)n * ldb + k0 + k4);
            sB[k4][n] = v.x; sB[k4+1][n] = v.y; sB[k4+2][n] = v.z; sB[k4+3][n] = v.w;
        }
        __syncthreads();
#pragma unroll
        for (int kk = 0; kk < 16; kk++) {
            const float4 a = *(const float4*)&sA[kk][ty << 2];
            const ulonglong2 bb = *(const ulonglong2*)&sB[kk][tx << 2];
            unsigned long long a0 = pk2(a.x, a.x), a1 = pk2(a.y, a.y), a2 = pk2(a.z, a.z), a3 = pk2(a.w, a.w);
            fma2(acc[0][0], a0, bb.x); fma2(acc[0][1], a0, bb.y);
            fma2(acc[1][0], a1, bb.x); fma2(acc[1][1], a1, bb.y);
            fma2(acc[2][0], a2, bb.x); fma2(acc[2][1], a2, bb.y);
            fma2(acc[3][0], a3, bb.x); fma2(acc[3][1], a3, bb.y);
        }
        __syncthreads();
    }
#pragma unroll
    for (int i = 0; i < 4; i++)
        *(ulonglong2*)(C + (size_t)((ty << 2) + i) * ldc + (tx << 2)) = *(ulonglong2*)acc[i];
}

// ============ Glue: Wfin partial per (b,h), SMEM-resident ============
__global__ void __launch_bounds__(256) k_glue(const float* __restrict__ Wq,
                                              const float* __restrict__ Wk,
                                              const float* __restrict__ Wo) {
    extern __shared__ float sf[];
    float* sG   = sf;            // 16384 (G, later T3)
    float* sWk  = sf + 16384;
    float* sWx  = sf + 24576;    // Wq then Wo
    float* sT13 = sf + 32768;
    float* sT2  = sf + 40960;
    float (*sA)[68] = (float(*)[68])(sf + 45056);
    float (*sB)[68] = (float(*)[68])(sf + 45056 + 16 * 68);
    const int t = threadIdx.x, z = blockIdx.x, b = z & 3, h = z >> 2;

    const float4* G4 = (const float4*)(g_G + (size_t)b * 16384);
    const float4* K4 = (const float4*)(Wk + (size_t)h * 64 * DM);
    const float4* Q4 = (const float4*)(Wq + (size_t)h * 64 * DM);
    for (int i = t; i < 4096; i += 256) ((float4*)sG)[i] = G4[i];
    for (int i = t; i < 2048; i += 256) { ((float4*)sWk)[i] = K4[i]; ((float4*)sWx)[i] = Q4[i]; }
    __syncthreads();
    gemm_tile<false, false>(sWk, sG,      sT13,      128, 128, 128, 128, sA, sB);
    gemm_tile<false, false>(sWk, sG + 64, sT13 + 64, 128, 128, 128, 128, sA, sB);
    __syncthreads();
    gemm_tile<false, true>(sT13, sWk, sT2, 128, 128, 128, 64, sA, sB);
    __syncthreads();
    gemm_tile<true, false>(sWx,      sT2, sG,           64, 128, 64, 64, sA, sB);
    gemm_tile<true, false>(sWx + 64, sT2, sG + 64 * 64, 64, 128, 64, 64, sA, sB);
    __syncthreads();
    for (int i = t; i < 8192; i += 256) sWx[i] = Wo[(size_t)(i >> 6) * 512 + h * 64 + (i & 63)];
    __syncthreads();
    float* P = g_part + (size_t)z * 16384;
#pragma unroll
    for (int m0 = 0; m0 < 128; m0 += 64)
#pragma unroll
        for (int n0 = 0; n0 < 128; n0 += 64)
            gemm_tile<false, true>(sG + m0 * 64, sWx + n0 * 64, P + (size_t)m0 * DM + n0,
                                   64, 64, 64, DM, sA, sB);
}

__global__ void __launch_bounds__(256) k_reduce_F() {
    const int i4 = blockIdx.x * 256 + threadIdx.x;  // 16384 float4s (64 blocks)
    const int b = i4 >> 12, e4 = i4 & 4095;
    float4 s = make_float4(0, 0, 0, 0);
#pragma unroll
    for (int hh = 0; hh < 8; hh++) {
        const float4 v = ((const float4*)g_part)[(size_t)(hh * 4 + b) * 4096 + e4];
        s.x += v.x; s.y += v.y; s.z += v.z; s.w += v.w;
    }
    const float c = 1.0f / (float)NT;
    ((float4*)g_Wfin)[i4] = make_float4(s.x * c, s.y * c, s.z * c, s.w * c);
}

// ============ out = Q @ Wfin + bo, bf16 3-split mma, double-buffered Q ============
__global__ void __launch_bounds__(256, 2) k_out(const float* __restrict__ q,
                                                const float* __restrict__ bo,
                                                float* __restrict__ out) {
    extern __shared__ __nv_bfloat16 sm[];
    __nv_bfloat16 (*sWh)[130]     = (__nv_bfloat16(*)[130])sm;
    __nv_bfloat16 (*sWl)[130]     = (__nv_bfloat16(*)[130])(sm + 64 * 130);
    __nv_bfloat16 (*sQh)[128][18] = (__nv_bfloat16(*)[128][18])(sm + 2 * 64 * 130);
    __nv_bfloat16 (*sQl)[128][18] = (__nv_bfloat16(*)[128][18])(sm + 2 * 64 * 130 + 2 * 128 * 18);
    const int t = threadIdx.x, w = t >> 5, lane = t & 31;
    const int g = lane >> 2, tg = lane & 3;
    const int n0 = blockIdx.y * 64, b = blockIdx.z;
    const float* Wf = g_Wfin + (size_t)b * DM * DM;
    const float* Qb = q + (size_t)b * NT * DM;
    float* Ob = out + (size_t)b * NT * DM;

    for (int i = t; i < 64 * 128; i += 256) {
        const int n = i & 63, k = i >> 6;
        __nv_bfloat16 h, l;
        split_bf(Wf[(size_t)k * DM + n0 + n], h, l);
        sWh[n][k] = h; sWl[n][k] = l;
    }
    __syncthreads();

    const int tok = t >> 2, kq = t & 3;
    const size_t base0 = (size_t)blockIdx.x * 2 * 128;
    float4 p0 = *(const float4*)(Qb + (base0 + tok) * DM + kq * 4);
    float4 p1 = *(const float4*)(Qb + (base0 + tok + 64) * DM + kq * 4);

    for (int bl = 0; bl < 2; bl++) {
        const size_t tok0 = base0 + (size_t)bl * 128;
        float acc[8][4] = {};
        for (int ks = 0; ks < 8; ks++) {
            const int bf = ks & 1;
#pragma unroll
            for (int j = 0; j < 4; j++) {
                __nv_bfloat16 h, l;
                split_bf(((const float*)&p0)[j], h, l); sQh[bf][tok][kq*4+j]    = h; sQl[bf][tok][kq*4+j]    = l;
                split_bf(((const float*)&p1)[j], h, l); sQh[bf][tok+64][kq*4+j] = h; sQl[bf][tok+64][kq*4+j] = l;
            }
            __syncthreads();   // single bar: next conv targets other buffer
            if (ks + 1 < 8) {
                p0 = *(const float4*)(Qb + (tok0 + tok) * DM + (ks + 1) * 16 + kq * 4);
                p1 = *(const float4*)(Qb + (tok0 + tok + 64) * DM + (ks + 1) * 16 + kq * 4);
            } else if (bl == 0) {
                p0 = *(const float4*)(Qb + (tok0 + 128 + tok) * DM + kq * 4);
                p1 = *(const float4*)(Qb + (tok0 + 128 + tok + 64) * DM + kq * 4);
            }
            const int m = w * 16 + g;
            uint32_t ah[4], al[4];
            ah[0] = *(const uint32_t*)&sQh[bf][m][2*tg];     ah[1] = *(const uint32_t*)&sQh[bf][m+8][2*tg];
            ah[2] = *(const uint32_t*)&sQh[bf][m][2*tg+8];   ah[3] = *(const uint32_t*)&sQh[bf][m+8][2*tg+8];
            al[0] = *(const uint32_t*)&sQl[bf][m][2*tg];     al[1] = *(const uint32_t*)&sQl[bf][m+8][2*tg];
            al[2] = *(const uint32_t*)&sQl[bf][m][2*tg+8];   al[3] = *(const uint32_t*)&sQl[bf][m+8][2*tg+8];
#pragma unroll
            for (int j = 0; j < 8; j++) {
                const int n = j * 8 + g, kb = ks * 16;
                uint32_t bh[2], bl2[2];
                bh[0]  = *(const uint32_t*)&sWh[n][kb + 2*tg];  bh[1]  = *(const uint32_t*)&sWh[n][kb + 2*tg + 8];
                bl2[0] = *(const uint32_t*)&sWl[n][kb + 2*tg];  bl2[1] = *(const uint32_t*)&sWl[n][kb + 2*tg + 8];
                mma_bf16(acc[j], ah, bh);
                mma_bf16(acc[j], ah, bl2);
                mma_bf16(acc[j], al, bh);
            }
        }
        const int m = w * 16 + g;
#pragma unroll
        for (int j = 0; j < 8; j++) {
            const int n = n0 + j * 8 + 2 * tg;
            const float2 bv = *(const float2*)(bo + n);
            *(float2*)(Ob + (tok0 + m) * DM + n)     = make_float2(acc[j][0] + bv.x, acc[j][1] + bv.y);
            *(float2*)(Ob + (tok0 + m + 8) * DM + n) = make_float2(acc[j][2] + bv.x, acc[j][3] + bv.y);
        }
    }
}

extern "C" void kernel_launch(void* const* d_in, const int* in_sizes, int n_in,
                              void* d_out, int out_size) {
    const float* queries = (const float*)d_in[0];
    const float* keys    = (const float*)d_in[1];
    const float* values  = (const float*)d_in[2];
    const float* Wq      = (const float*)d_in[3];
    const float* Wk      = (const float*)d_in[4];
    const float* Wo      = (const float*)d_in[5];
    const float* bo      = (const float*)d_in[6];
    float* out = (float*)d_out;

    const int out_smem = (2 * 64 * 130 + 4 * 128 * 18) * 2;  // 51,712 B
    cudaFuncSetAttribute(k_glue, cudaFuncAttributeMaxDynamicSharedMemorySize, 188928);
    cudaFuncSetAttribute(k_out,  cudaFuncAttributeMaxDynamicSharedMemorySize, out_smem);

    k_g       <<<dim3(SPG, B_), 256>>>(keys, values);
    k_reduce_G<<<64, 256>>>();
    k_glue    <<<32, 256, 188928>>>(Wq, Wk, Wo);
    k_reduce_F<<<64, 256>>>();
    k_out     <<<dim3(64, 2, B_), 256, out_smem>>>(queries, bo, out);
}

// round 10
// speedup vs baseline: 1.0618x; 1.0114x over previous
#include <cuda_runtime.h>
#include <cuda_bf16.h>
#include <cstdint>
#include <cstddef>

#define B_ 4
#define NT 16384
#define DM 128
#define SPG 74   // G splits per batch

static __device__ float g_part[SPG * B_ * DM * DM];
static __device__ float g_G4 [4 * B_ * DM * DM];   // 4-group G partial sums
static __device__ float g_Wfin[B_ * DM * DM];
static __device__ float g_C[8 * DM * DM];          // C_h = Wq_h^T Wk_h
static __device__ float g_D[8 * DM * DM];          // D_h = Wk_h^T Wo_h^T

// ---------- helpers ----------
__device__ __forceinline__ unsigned long long pk2(float x, float y) {
    unsigned long long r; asm("mov.b64 %0, {%1,%2};" : "=l"(r) : "f"(x), "f"(y)); return r;
}
__device__ __forceinline__ void fma2(unsigned long long& c, unsigned long long a, unsigned long long b) {
    asm("fma.rn.f32x2 %0, %1, %2, %3;" : "=l"(c) : "l"(a), "l"(b), "l"(c));
}
__device__ __forceinline__ float2 up2(unsigned long long v) {
    float2 f; asm("mov.b64 {%0,%1}, %2;" : "=f"(f.x), "=f"(f.y) : "l"(v)); return f;
}
__device__ __forceinline__ void split_bf(float x, __nv_bfloat16& h, __nv_bfloat16& l) {
    h = __float2bfloat16(x);
    l = __float2bfloat16(x - __bfloat162float(h));
}
__device__ __forceinline__ void mma_bf16(float* c, const uint32_t* a, const uint32_t* b) {
    asm("mma.sync.aligned.m16n8k16.row.col.f32.bf16.bf16.f32 "
        "{%0,%1,%2,%3},{%4,%5,%6,%7},{%8,%9},{%0,%1,%2,%3};"
        : "+f"(c[0]), "+f"(c[1]), "+f"(c[2]), "+f"(c[3])
        : "r"(a[0]), "r"(a[1]), "r"(a[2]), "r"(a[3]), "r"(b[0]), "r"(b[1]));
}

// ---------- fp32 fma2 64x64 tile ----------
template <bool TA, bool TB>
__device__ __forceinline__ void gemm_tile(const float* A, const float* B, float* C, int K,
                                          int lda, int ldb, int ldc, float (*sA)[68], float (*sB)[68]) {
    const int t = threadIdx.x, tx = t & 15, ty = t >> 4;
    unsigned long long acc[4][2] = {};
    for (int k0 = 0; k0 < K; k0 += 16) {
        if (TA) {
            const int kk = t >> 4, m4 = (t & 15) << 2;
            *(float4*)&sA[kk][m4] = *(const float4*)(A + (size_t)(k0 + kk) * lda + m4);
        } else {
            const int m = t >> 2, k4 = (t & 3) << 2;
            float4 v = *(const float4*)(A + (size_t)m * lda + k0 + k4);
            sA[k4][m] = v.x; sA[k4+1][m] = v.y; sA[k4+2][m] = v.z; sA[k4+3][m] = v.w;
        }
        if (!TB) {
            const int kk = t >> 4, n4 = (t & 15) << 2;
            *(float4*)&sB[kk][n4] = *(const float4*)(B + (size_t)(k0 + kk) * ldb + n4);
        } else {
            const int n = t >> 2, k4 = (t & 3) << 2;
            float4 v = *(const float4*)(B + (size_t)n * ldb + k0 + k4);
            sB[k4][n] = v.x; sB[k4+1][n] = v.y; sB[k4+2][n] = v.z; sB[k4+3][n] = v.w;
        }
        __syncthreads();
#pragma unroll
        for (int kk = 0; kk < 16; kk++) {
            const float4 a = *(const float4*)&sA[kk][ty << 2];
            const ulonglong2 bb = *(const ulonglong2*)&sB[kk][tx << 2];
            unsigned long long a0 = pk2(a.x, a.x), a1 = pk2(a.y, a.y), a2 = pk2(a.z, a.z), a3 = pk2(a.w, a.w);
            fma2(acc[0][0], a0, bb.x); fma2(acc[0][1], a0, bb.y);
            fma2(acc[1][0], a1, bb.x); fma2(acc[1][1], a1, bb.y);
            fma2(acc[2][0], a2, bb.x); fma2(acc[2][1], a2, bb.y);
            fma2(acc[3][0], a3, bb.x); fma2(acc[3][1], a3, bb.y);
        }
        __syncthreads();
    }
#pragma unroll
    for (int i = 0; i < 4; i++)
        *(ulonglong2*)(C + (size_t)((ty << 2) + i) * ldc + (tx << 2)) = *(ulonglong2*)acc[i];
}

// ============ k_g: y<4 -> bf16 G partials; y==4 -> C_h/D_h precompute ============
__global__ void __launch_bounds__(256, 2) k_g(const float* __restrict__ keys,
                                              const float* __restrict__ values,
                                              const float* __restrict__ Wq,
                                              const float* __restrict__ Wk,
                                              const float* __restrict__ Wo) {
    __shared__ __nv_bfloat16 sKh[2][DM][18], sKl[2][DM][18], sVh[2][DM][18], sVl[2][DM][18];
    __shared__ float sA[16][68], sB[16][68];
    const int sp = blockIdx.x, b = blockIdx.y;
    const int t = threadIdx.x;

    if (b == 4) {   // C/D precompute on 16 spare CTAs
        if (sp >= 16) return;
        const int h = sp & 7;
        if (sp < 8) {  // C_h = Wq_h^T Wk_h  (K=64)
#pragma unroll
            for (int m0 = 0; m0 < 128; m0 += 64)
#pragma unroll
                for (int n0 = 0; n0 < 128; n0 += 64)
                    gemm_tile<true, false>(Wq + (size_t)h * 64 * DM + m0,
                                           Wk + (size_t)h * 64 * DM + n0,
                                           g_C + (size_t)h * 16384 + (size_t)m0 * DM + n0,
                                           64, DM, DM, DM, sA, sB);
        } else {       // D_h = Wk_h^T Wo_h^T (K=64)
#pragma unroll
            for (int m0 = 0; m0 < 128; m0 += 64)
#pragma unroll
                for (int n0 = 0; n0 < 128; n0 += 64)
                    gemm_tile<true, true>(Wk + (size_t)h * 64 * DM + m0,
                                          Wo + (size_t)n0 * 512 + h * 64,
                                          g_D + (size_t)h * 16384 + (size_t)m0 * DM + n0,
                                          64, DM, 512, DM, sA, sB);
        }
        return;
    }

    const int w = t >> 5, lane = t & 31;
    const int g = lane >> 2, tg = lane & 3;
    const int c0 = (sp * 1024) / SPG, c1 = ((sp + 1) * 1024) / SPG;
    const float* Kb = keys   + (size_t)b * NT * DM;
    const float* Vb = values + (size_t)b * NT * DM;

    float acc[16][4] = {};
    const int m4 = (t & 31) << 2, tr = t >> 5;
    const float* Kc = Kb + (size_t)c0 * 16 * DM;
    const float* Vc = Vb + (size_t)c0 * 16 * DM;
    float4 pk0 = *(const float4*)(Kc + (size_t)tr * DM + m4);
    float4 pk1 = *(const float4*)(Kc + (size_t)(tr + 8) * DM + m4);
    float4 pv0 = *(const float4*)(Vc + (size_t)tr * DM + m4);
    float4 pv1 = *(const float4*)(Vc + (size_t)(tr + 8) * DM + m4);

    for (int c = c0; c < c1; c++) {
        const int bf = (c - c0) & 1;
#pragma unroll
        for (int j = 0; j < 4; j++) {
            __nv_bfloat16 h, l;
            split_bf(((const float*)&pk0)[j], h, l); sKh[bf][m4+j][tr]   = h; sKl[bf][m4+j][tr]   = l;
            split_bf(((const float*)&pk1)[j], h, l); sKh[bf][m4+j][tr+8] = h; sKl[bf][m4+j][tr+8] = l;
            split_bf(((const float*)&pv0)[j], h, l); sVh[bf][m4+j][tr]   = h; sVl[bf][m4+j][tr]   = l;
            split_bf(((const float*)&pv1)[j], h, l); sVh[bf][m4+j][tr+8] = h; sVl[bf][m4+j][tr+8] = l;
        }
        __syncthreads();
        if (c + 1 < c1) {
            const float* Kn = Kb + (size_t)(c + 1) * 16 * DM;
            const float* Vn = Vb + (size_t)(c + 1) * 16 * DM;
            pk0 = *(const float4*)(Kn + (size_t)tr * DM + m4);
            pk1 = *(const float4*)(Kn + (size_t)(tr + 8) * DM + m4);
            pv0 = *(const float4*)(Vn + (size_t)tr * DM + m4);
            pv1 = *(const float4*)(Vn + (size_t)(tr + 8) * DM + m4);
        }
        const int m = w * 16 + g;
        uint32_t ah[4], al[4];
        ah[0] = *(const uint32_t*)&sKh[bf][m][2*tg];     ah[1] = *(const uint32_t*)&sKh[bf][m+8][2*tg];
        ah[2] = *(const uint32_t*)&sKh[bf][m][2*tg+8];   ah[3] = *(const uint32_t*)&sKh[bf][m+8][2*tg+8];
        al[0] = *(const uint32_t*)&sKl[bf][m][2*tg];     al[1] = *(const uint32_t*)&sKl[bf][m+8][2*tg];
        al[2] = *(const uint32_t*)&sKl[bf][m][2*tg+8];   al[3] = *(const uint32_t*)&sKl[bf][m+8][2*tg+8];
#pragma unroll
        for (int j = 0; j < 16; j++) {
            const int n = j * 8 + g;
            uint32_t bh[2], bl[2];
            bh[0] = *(const uint32_t*)&sVh[bf][n][2*tg]; bh[1] = *(const uint32_t*)&sVh[bf][n][2*tg+8];
            bl[0] = *(const uint32_t*)&sVl[bf][n][2*tg]; bl[1] = *(const uint32_t*)&sVl[bf][n][2*tg+8];
            mma_bf16(acc[j], ah, bh);
            mma_bf16(acc[j], ah, bl);
            mma_bf16(acc[j], al, bh);
        }
    }
    float* C = g_part + ((size_t)b * SPG + sp) * 16384;
    const int m = w * 16 + g;
#pragma unroll
    for (int j = 0; j < 16; j++) {
        const int n = j * 8 + 2 * tg;
        *(float2*)(C + (size_t)m * DM + n)       = make_float2(acc[j][0], acc[j][1]);
        *(float2*)(C + (size_t)(m + 8) * DM + n) = make_float2(acc[j][2], acc[j][3]);
    }
}

// ============ reduce_G, 4 groups of 18-19 partials, 256 CTAs ============
__global__ void __launch_bounds__(256) k_reduce_G4() {
    const int i4 = blockIdx.x * 256 + threadIdx.x;  // 16384 float4s per group
    const int gi = blockIdx.y;
    const int b = i4 >> 12, e4 = i4 & 4095;
    const int lo = (gi * SPG) / 4, hi = ((gi + 1) * SPG) / 4;
    float4 s = make_float4(0, 0, 0, 0);
#pragma unroll 4
    for (int sp = lo; sp < hi; sp++) {
        const float4 v = ((const float4*)g_part)[((size_t)b * SPG + sp) * 4096 + e4];
        s.x += v.x; s.y += v.y; s.z += v.z; s.w += v.w;
    }
    ((float4*)g_G4)[((size_t)gi * 4 + b) * 4096 + e4] = s;
}

// ============ glue2: per (b,h,half)  P-half = (C_h[half] G_b) D_h,  64 CTAs ============
__global__ void __launch_bounds__(256) k_glue2() {
    extern __shared__ float sf[];
    float* sG = sf;              // 16384 floats
    float* sE = sf + 16384;      // 8192 floats (64x128)
    float (*sA)[68] = (float(*)[68])(sf + 24576);
    float (*sB)[68] = (float(*)[68])(sf + 24576 + 16 * 68);
    const int t = threadIdx.x, z = blockIdx.x;
    const int b = z & 3, h = (z >> 2) & 7, half = z >> 5;

    for (int i = t; i < 4096; i += 256) {   // G_b = sum of 4 group partials
        float4 s = make_float4(0, 0, 0, 0);
#pragma unroll
        for (int gi = 0; gi < 4; gi++) {
            const float4 v = ((const float4*)g_G4)[((size_t)gi * 4 + b) * 4096 + i];
            s.x += v.x; s.y += v.y; s.z += v.z; s.w += v.w;
        }
        ((float4*)sG)[i] = s;
    }
    __syncthreads();
    const float* Ch = g_C + (size_t)h * 16384 + (size_t)half * 64 * DM;
#pragma unroll
    for (int n0 = 0; n0 < 128; n0 += 64)
        gemm_tile<false, false>(Ch, sG + n0, sE + n0, 128, DM, DM, DM, sA, sB);
    __syncthreads();
    const float* Dh = g_D + (size_t)h * 16384;
    float* P = g_part + (size_t)(h * 4 + b) * 16384 + (size_t)half * 64 * DM;
#pragma unroll
    for (int n0 = 0; n0 < 128; n0 += 64)
        gemm_tile<false, false>(sE, Dh + n0, P + n0, 128, DM, DM, DM, sA, sB);
}

__global__ void __launch_bounds__(256) k_reduce_F() {
    const int i4 = blockIdx.x * 256 + threadIdx.x;  // 16384 float4s (64 blocks)
    const int b = i4 >> 12, e4 = i4 & 4095;
    float4 s = make_float4(0, 0, 0, 0);
#pragma unroll
    for (int hh = 0; hh < 8; hh++) {
        const float4 v = ((const float4*)g_part)[(size_t)(hh * 4 + b) * 4096 + e4];
        s.x += v.x; s.y += v.y; s.z += v.z; s.w += v.w;
    }
    const float c = 1.0f / (float)NT;
    ((float4*)g_Wfin)[i4] = make_float4(s.x * c, s.y * c, s.z * c, s.w * c);
}

// ============ out = Q @ Wfin + bo, bf16 3-split mma, coalesced stores ============
__global__ void __launch_bounds__(256, 2) k_out(const float* __restrict__ q,
                                                const float* __restrict__ bo,
                                                float* __restrict__ out) {
    extern __shared__ __nv_bfloat16 sm[];
    __nv_bfloat16 (*sWh)[130]     = (__nv_bfloat16(*)[130])sm;
    __nv_bfloat16 (*sWl)[130]     = (__nv_bfloat16(*)[130])(sm + 64 * 130);
    __nv_bfloat16 (*sQh)[128][18] = (__nv_bfloat16(*)[128][18])(sm + 2 * 64 * 130);
    __nv_bfloat16 (*sQl)[128][18] = (__nv_bfloat16(*)[128][18])(sm + 2 * 64 * 130 + 2 * 128 * 18);
    const int t = threadIdx.x, w = t >> 5, lane = t & 31;
    const int g = lane >> 2, tg = lane & 3;
    const int n0 = blockIdx.y * 64, b = blockIdx.z;
    const float* Wf = g_Wfin + (size_t)b * DM * DM;
    const float* Qb = q + (size_t)b * NT * DM;
    float* Ob = out + (size_t)b * NT * DM;

    for (int i = t; i < 64 * 128; i += 256) {
        const int n = i & 63, k = i >> 6;
        __nv_bfloat16 h, l;
        split_bf(Wf[(size_t)k * DM + n0 + n], h, l);
        sWh[n][k] = h; sWl[n][k] = l;
    }
    __syncthreads();

    const int tok = t >> 2, kq = t & 3;
    const size_t base0 = (size_t)blockIdx.x * 2 * 128;
    float4 p0 = *(const float4*)(Qb + (base0 + tok) * DM + kq * 4);
    float4 p1 = *(const float4*)(Qb + (base0 + tok + 64) * DM + kq * 4);

    for (int bl = 0; bl < 2; bl++) {
        const size_t tok0 = base0 + (size_t)bl * 128;
        float acc[8][4] = {};
        for (int ks = 0; ks < 8; ks++) {
            const int bf = ks & 1;
#pragma unroll
            for (int j = 0; j < 4; j++) {
                __nv_bfloat16 h, l;
                split_bf(((const float*)&p0)[j], h, l); sQh[bf][tok][kq*4+j]    = h; sQl[bf][tok][kq*4+j]    = l;
                split_bf(((const float*)&p1)[j], h, l); sQh[bf][tok+64][kq*4+j] = h; sQl[bf][tok+64][kq*4+j] = l;
            }
            __syncthreads();
            if (ks + 1 < 8) {
                p0 = *(const float4*)(Qb + (tok0 + tok) * DM + (ks + 1) * 16 + kq * 4);
                p1 = *(const float4*)(Qb + (tok0 + tok + 64) * DM + (ks + 1) * 16 + kq * 4);
            } else if (bl == 0) {
                p0 = *(const float4*)(Qb + (tok0 + 128 + tok) * DM + kq * 4);
                p1 = *(const float4*)(Qb + (tok0 + 128 + tok + 64) * DM + kq * 4);
            }
            const int m = w * 16 + g;
            uint32_t ah[4], al[4];
            ah[0] = *(const uint32_t*)&sQh[bf][m][2*tg];     ah[1] = *(const uint32_t*)&sQh[bf][m+8][2*tg];
            ah[2] = *(const uint32_t*)&sQh[bf][m][2*tg+8];   ah[3] = *(const uint32_t*)&sQh[bf][m+8][2*tg+8];
            al[0] = *(const uint32_t*)&sQl[bf][m][2*tg];     al[1] = *(const uint32_t*)&sQl[bf][m+8][2*tg];
            al[2] = *(const uint32_t*)&sQl[bf][m][2*tg+8];   al[3] = *(const uint32_t*)&sQl[bf][m+8][2*tg+8];
#pragma unroll
            for (int j = 0; j < 8; j++) {
                const int n = j * 8 + g, kb = ks * 16;
                uint32_t bh[2], bl2[2];
                bh[0]  = *(const uint32_t*)&sWh[n][kb + 2*tg];  bh[1]  = *(const uint32_t*)&sWh[n][kb + 2*tg + 8];
                bl2[0] = *(const uint32_t*)&sWl[n][kb + 2*tg];  bl2[1] = *(const uint32_t*)&sWl[n][kb + 2*tg + 8];
                mma_bf16(acc[j], ah, bh);
                mma_bf16(acc[j], ah, bl2);
                mma_bf16(acc[j], al, bh);
            }
        }
        const int m = w * 16 + g;
#pragma unroll
        for (int j = 0; j < 8; j++) {
            const int n = n0 + j * 8 + 2 * tg;
            const float2 bv = *(const float2*)(bo + n);
            const float r0 = acc[j][0] + bv.x, r1 = acc[j][1] + bv.y;  // row m
            const float r2 = acc[j][2] + bv.x, r3 = acc[j][3] + bv.y;  // row m+8
            const unsigned long long y01 = __shfl_xor_sync(0xffffffffu, pk2(r0, r1), 1);
            const unsigned long long y23 = __shfl_xor_sync(0xffffffffu, pk2(r2, r3), 1);
            if ((tg & 1) == 0) {
                const float2 p = up2(y01);
                *(float4*)(Ob + (tok0 + m) * DM + n) = make_float4(r0, r1, p.x, p.y);
            } else {
                const float2 p = up2(y23);
                *(float4*)(Ob + (tok0 + m + 8) * DM + (n - 2)) = make_float4(p.x, p.y, r2, r3);
            }
        }
    }
}

extern "C" void kernel_launch(void* const* d_in, const int* in_sizes, int n_in,
                              void* d_out, int out_size) {
    const float* queries = (const float*)d_in[0];
    const float* keys    = (const float*)d_in[1];
    const float* values  = (const float*)d_in[2];
    const float* Wq      = (const float*)d_in[3];
    const float* Wk      = (const float*)d_in[4];
    const float* Wo      = (const float*)d_in[5];
    const float* bo      = (const float*)d_in[6];
    float* out = (float*)d_out;

    const int glue_smem = (16384 + 8192 + 2 * 16 * 68) * 4;  // 107,008 B
    const int out_smem  = (2 * 64 * 130 + 4 * 128 * 18) * 2; // 51,712 B
    cudaFuncSetAttribute(k_glue2, cudaFuncAttributeMaxDynamicSharedMemorySize, glue_smem);
    cudaFuncSetAttribute(k_out,   cudaFuncAttributeMaxDynamicSharedMemorySize, out_smem);

    k_g        <<<dim3(SPG, 5), 256>>>(keys, values, Wq, Wk, Wo);
    k_reduce_G4<<<dim3(64, 4), 256>>>();
    k_glue2    <<<64, 256, glue_smem>>>();
    k_reduce_F <<<64, 256>>>();
    k_out      <<<dim3(64, 2, B_), 256, out_smem>>>(queries, bo, out);
}